// round 1
// baseline (speedup 1.0000x reference)
#include <cuda_runtime.h>
#include <math.h>

#define D 70
#define NMAX 50000
#define EMAX 800000
#define GG 128

// ---------------- device scratch (static, no allocation) ----------------
__device__ float g_h[NMAX * D];
__device__ float g_A[NMAX * D];
__device__ float g_B[NMAX * D];
__device__ float g_Dh[NMAX * D];
__device__ float g_Eh[NMAX * D];
__device__ float g_num[NMAX * D];
__device__ float g_den[NMAX * D];
__device__ float g_hraw[NMAX * D];
__device__ float g_e[EMAX * D];
__device__ float g_enew[EMAX * D];
__device__ double g_stats[4 * D];   // [hsum, hsq, esum, esq]
__device__ float g_norm[4 * D];     // [mu_h, rstd_h, mu_e, rstd_e]
__device__ float g_hg[GG * D];
__device__ float g_cnt[GG];

// ---------------- zero kernels ----------------
__global__ void zero_layer_kernel(int n) {
    int i = blockIdx.x * blockDim.x + threadIdx.x;
    int stride = gridDim.x * blockDim.x;
    for (int idx = i; idx < n; idx += stride) { g_num[idx] = 0.f; g_den[idx] = 0.f; }
    if (i < 4 * D) g_stats[i] = 0.0;
}

__global__ void zero_readout_kernel() {
    int i = blockIdx.x * blockDim.x + threadIdx.x;
    if (i < GG * D) g_hg[i] = 0.f;
    if (i < GG) g_cnt[i] = 0.f;
}

// ---------------- generic [M,K]@[K,70]+b GEMM, 64-row tiles ----------------
// blockDim (14,16): thread covers 4 rows x 5 cols.
template <int K>
__global__ void gemm70_kernel(const float* __restrict__ X, const float* __restrict__ W,
                              const float* __restrict__ bias, float* __restrict__ Y, int M) {
    extern __shared__ float smem[];
    float* sW = smem;            // K*70
    float* sX = smem + K * D;    // 64*K
    __shared__ float sb[D];
    const int tx = threadIdx.x, ty = threadIdx.y;
    const int tid = ty * 14 + tx;
    for (int i = tid; i < K * D; i += 224) sW[i] = W[i];
    if (tid < D) sb[tid] = bias[tid];
    __syncthreads();

    const int base = blockIdx.x * 64;
    const int cnt = min(64, M - base);
    for (int i = tid; i < cnt * K; i += 224) sX[i] = X[(size_t)base * K + i];
    __syncthreads();

    const int c0 = tx * 5, r0 = ty * 4;
    float acc[4][5];
#pragma unroll
    for (int r = 0; r < 4; r++)
#pragma unroll
        for (int c = 0; c < 5; c++) acc[r][c] = sb[c0 + c];

#pragma unroll 2
    for (int k = 0; k < K; k++) {
        float w0 = sW[k * D + c0 + 0], w1 = sW[k * D + c0 + 1], w2 = sW[k * D + c0 + 2];
        float w3 = sW[k * D + c0 + 3], w4 = sW[k * D + c0 + 4];
#pragma unroll
        for (int r = 0; r < 4; r++) {
            float xv = sX[(r0 + r) * K + k];
            acc[r][0] += xv * w0; acc[r][1] += xv * w1; acc[r][2] += xv * w2;
            acc[r][3] += xv * w3; acc[r][4] += xv * w4;
        }
    }
#pragma unroll
    for (int r = 0; r < 4; r++) {
        int row = base + r0 + r;
        if (row < M) {
#pragma unroll
            for (int c = 0; c < 5; c++) Y[(size_t)row * D + c0 + c] = acc[r][c];
        }
    }
}

// ---------------- edge embedding: e = ef * Wemb_e + bemb_e ----------------
__global__ void embed_e_kernel(const float* __restrict__ ef, const float* __restrict__ W,
                               const float* __restrict__ b, int E_) {
    int j = threadIdx.x;
    float w = W[j], bb = b[j];
    for (int row = blockIdx.x * blockDim.y + threadIdx.y; row < E_; row += gridDim.x * blockDim.y)
        g_e[(size_t)row * D + j] = ef[row] * w + bb;
}

// ---------------- fused edge kernel ----------------
// Per edge: Ce = e@WC + bC ; e_new = Dh[src]+Eh[dst]+Ce ; sigma = sigmoid(e_new);
// atomics into num/den ; store e_new*snorm_e ; accumulate BN stats (if storeE).
__global__ __launch_bounds__(224) void edge_kernel(
    const float* __restrict__ e, const float* __restrict__ WC, const float* __restrict__ bC,
    const float* __restrict__ Dh, const float* __restrict__ Eh, const float* __restrict__ Bh,
    const int* __restrict__ src, const int* __restrict__ dst, const float* __restrict__ snorm_e,
    float* __restrict__ enew, int E_, int storeE) {
    __shared__ float sW[D * D];
    __shared__ float sb[D];
    __shared__ __align__(8) float sX[64 * D];
    __shared__ int sS[64], sT[64];
    const int tx = threadIdx.x, ty = threadIdx.y;
    const int tid = ty * 14 + tx;
    for (int i = tid; i < D * D; i += 224) sW[i] = WC[i];
    if (tid < D) sb[tid] = bC[tid];
    __syncthreads();

    const int c0 = tx * 5, r0 = ty * 4;
    float lsum[5] = {0, 0, 0, 0, 0}, lsq[5] = {0, 0, 0, 0, 0};

    for (int base = blockIdx.x * 64; base < E_; base += gridDim.x * 64) {
        int cnt = min(64, E_ - base);
        for (int i = tid; i < cnt * D; i += 224) sX[i] = e[(size_t)base * D + i];
        for (int i = tid; i < cnt; i += 224) { sS[i] = src[base + i]; sT[i] = dst[base + i]; }
        __syncthreads();

        float acc[4][5];
#pragma unroll
        for (int r = 0; r < 4; r++)
#pragma unroll
            for (int c = 0; c < 5; c++) acc[r][c] = sb[c0 + c];

#pragma unroll 2
        for (int k = 0; k < D; k++) {
            float w0 = sW[k * D + c0 + 0], w1 = sW[k * D + c0 + 1], w2 = sW[k * D + c0 + 2];
            float w3 = sW[k * D + c0 + 3], w4 = sW[k * D + c0 + 4];
#pragma unroll
            for (int r = 0; r < 4; r++) {
                float xv = sX[(r0 + r) * D + k];
                acc[r][0] += xv * w0; acc[r][1] += xv * w1; acc[r][2] += xv * w2;
                acc[r][3] += xv * w3; acc[r][4] += xv * w4;
            }
        }

#pragma unroll
        for (int r = 0; r < 4; r++) {
            int ei = base + r0 + r;
            if (ei < E_) {
                int s = sS[r0 + r], d2 = sT[r0 + r];
                float sn = snorm_e[ei];
                const float* dhp = Dh + (size_t)s * D + c0;
                const float* ehp = Eh + (size_t)d2 * D + c0;
                const float* bhp = Bh + (size_t)s * D + c0;
                float* nump = g_num + (size_t)d2 * D + c0;
                float* denp = g_den + (size_t)d2 * D + c0;
#pragma unroll
                for (int c = 0; c < 5; c++) {
                    float en = acc[r][c] + dhp[c] + ehp[c];
                    float sg = 1.f / (1.f + __expf(-en));
                    atomicAdd(nump + c, bhp[c] * sg);
                    atomicAdd(denp + c, sg);
                    if (storeE) {
                        float ens = en * sn;
                        enew[(size_t)ei * D + c0 + c] = ens;
                        lsum[c] += ens; lsq[c] += ens * ens;
                    }
                }
            }
        }
        __syncthreads();
    }

    if (storeE) {
        double* dsc = (double*)sX;  // 16*70 doubles = 8960B <= 17920B
#pragma unroll
        for (int c = 0; c < 5; c++) dsc[ty * D + c0 + c] = (double)lsum[c];
        __syncthreads();
        if (ty == 0) {
#pragma unroll
            for (int c = 0; c < 5; c++) {
                double s = 0;
                for (int yy = 0; yy < 16; yy++) s += dsc[yy * D + c0 + c];
                atomicAdd(&g_stats[2 * D + c0 + c], s);
            }
        }
        __syncthreads();
#pragma unroll
        for (int c = 0; c < 5; c++) dsc[ty * D + c0 + c] = (double)lsq[c];
        __syncthreads();
        if (ty == 0) {
#pragma unroll
            for (int c = 0; c < 5; c++) {
                double s = 0;
                for (int yy = 0; yy < 16; yy++) s += dsc[yy * D + c0 + c];
                atomicAdd(&g_stats[3 * D + c0 + c], s);
            }
        }
    }
}

// ---------------- h combine: hraw = (A + num/(den+eps))*snorm_n, + BN stats ----------------
__global__ void hcombine_kernel(const float* __restrict__ A, const float* __restrict__ snorm, int Nn) {
    int j = threadIdx.x, ty = threadIdx.y;  // (70,8)
    float ls = 0.f, lq = 0.f;
    for (int row = blockIdx.x * 8 + ty; row < Nn; row += gridDim.x * 8) {
        size_t idx = (size_t)row * D + j;
        float v = (A[idx] + g_num[idx] / (g_den[idx] + 1e-6f)) * snorm[row];
        g_hraw[idx] = v;
        ls += v; lq += v * v;
    }
    __shared__ float s1[8][D];
    s1[ty][j] = ls;
    __syncthreads();
    if (ty == 0) {
        float s = ls;
        for (int yy = 1; yy < 8; yy++) s += s1[yy][j];
        atomicAdd(&g_stats[j], (double)s);
    }
    __syncthreads();
    s1[ty][j] = lq;
    __syncthreads();
    if (ty == 0) {
        float s = lq;
        for (int yy = 1; yy < 8; yy++) s += s1[yy][j];
        atomicAdd(&g_stats[D + j], (double)s);
    }
}

__global__ void finalize_kernel(int Nn, int E_) {
    int j = threadIdx.x;
    if (j < D) {
        double mu = g_stats[j] / Nn;
        double var = g_stats[D + j] / Nn - mu * mu;
        g_norm[j] = (float)mu;
        g_norm[D + j] = rsqrtf(fmaxf((float)var, 0.f) + 1e-5f);
        double mue = g_stats[2 * D + j] / E_;
        double vare = g_stats[3 * D + j] / E_ - mue * mue;
        g_norm[2 * D + j] = (float)mue;
        g_norm[3 * D + j] = rsqrtf(fmaxf((float)vare, 0.f) + 1e-5f);
    }
}

__global__ void happly_kernel(const float* __restrict__ gamma, const float* __restrict__ beta, int Nn) {
    int j = threadIdx.x;
    float mu = g_norm[j], rs = g_norm[D + j], ga = gamma[j], bb = beta[j];
    for (int row = blockIdx.x * 8 + threadIdx.y; row < Nn; row += gridDim.x * 8) {
        size_t idx = (size_t)row * D + j;
        float v = (g_hraw[idx] - mu) * rs * ga + bb;
        g_h[idx] += fmaxf(v, 0.f);
    }
}

__global__ void eapply_kernel(const float* __restrict__ gamma, const float* __restrict__ beta, int E_) {
    int j = threadIdx.x;
    float mu = g_norm[2 * D + j], rs = g_norm[3 * D + j], ga = gamma[j], bb = beta[j];
    for (int row = blockIdx.x * 8 + threadIdx.y; row < E_; row += gridDim.x * 8) {
        size_t idx = (size_t)row * D + j;
        float v = (g_enew[idx] - mu) * rs * ga + bb;
        g_e[idx] += fmaxf(v, 0.f);
    }
}

// ---------------- readout ----------------
__global__ void scatter_kernel(const int* __restrict__ gid, int Nn) {
    int j = threadIdx.x;
    for (int row = blockIdx.x * 8 + threadIdx.y; row < Nn; row += gridDim.x * 8) {
        int g = gid[row];
        atomicAdd(&g_hg[g * D + j], g_h[(size_t)row * D + j]);
        if (j == 0) atomicAdd(&g_cnt[g], 1.f);
    }
}

__global__ void mlp_kernel(const float* __restrict__ W0, const float* __restrict__ b0,
                           const float* __restrict__ W1, const float* __restrict__ b1,
                           const float* __restrict__ W2, const float* __restrict__ b2,
                           float* __restrict__ out) {
    int g = threadIdx.x;
    if (g >= GG) return;
    float cnt = fmaxf(g_cnt[g], 1.f);
    float x[D];
#pragma unroll
    for (int k = 0; k < D; k++) x[k] = g_hg[g * D + k] / cnt;
    float y0[35];
#pragma unroll
    for (int o = 0; o < 35; o++) {
        float s = b0[o];
#pragma unroll
        for (int k = 0; k < D; k++) s += x[k] * W0[k * 35 + o];
        y0[o] = fmaxf(s, 0.f);
    }
    float y1[17];
#pragma unroll
    for (int o = 0; o < 17; o++) {
        float s = b1[o];
#pragma unroll
        for (int k = 0; k < 35; k++) s += y0[k] * W1[k * 17 + o];
        y1[o] = fmaxf(s, 0.f);
    }
#pragma unroll
    for (int o = 0; o < 10; o++) {
        float s = b2[o];
#pragma unroll
        for (int k = 0; k < 17; k++) s += y1[k] * W2[k * 10 + o];
        out[g * 10 + o] = s;
    }
}

// ---------------- host ----------------
extern "C" void kernel_launch(void* const* d_in, const int* in_sizes, int n_in,
                              void* d_out, int out_size) {
    const float* nodes   = (const float*)d_in[0];
    const float* ef      = (const float*)d_in[1];
    const float* snorm_n = (const float*)d_in[2];
    const float* snorm_e = (const float*)d_in[3];
    const int N = in_sizes[2];
    const int E_ = in_sizes[3];

    const int *src, *dst, *gid;
    const float *Wemb_h, *bemb_h, *Wemb_e, *bemb_e;
    const float *WA, *bA, *WB, *bB, *WC, *bC, *WDl, *bDl, *WEl, *bEl;
    const float *gh, *bh, *ge, *be, *W0, *b0, *W1, *b1, *W2, *b2;

    if (in_sizes[4] == E_) {
        // setup_inputs dict order
        src = (const int*)d_in[4]; dst = (const int*)d_in[5]; gid = (const int*)d_in[6];
        Wemb_h = (const float*)d_in[7];  bemb_h = (const float*)d_in[8];
        Wemb_e = (const float*)d_in[9];  bemb_e = (const float*)d_in[10];
        WA = (const float*)d_in[11]; bA = (const float*)d_in[12];
        WB = (const float*)d_in[13]; bB = (const float*)d_in[14];
        WC = (const float*)d_in[15]; bC = (const float*)d_in[16];
        WDl = (const float*)d_in[17]; bDl = (const float*)d_in[18];
        WEl = (const float*)d_in[19]; bEl = (const float*)d_in[20];
        gh = (const float*)d_in[21]; bh = (const float*)d_in[22];
        ge = (const float*)d_in[23]; be = (const float*)d_in[24];
        W0 = (const float*)d_in[25]; b0 = (const float*)d_in[26];
        W1 = (const float*)d_in[27]; b1 = (const float*)d_in[28];
        W2 = (const float*)d_in[29]; b2 = (const float*)d_in[30];
    } else {
        // reference() signature order
        Wemb_h = (const float*)d_in[4];  bemb_h = (const float*)d_in[5];
        Wemb_e = (const float*)d_in[6];  bemb_e = (const float*)d_in[7];
        WA = (const float*)d_in[8];  bA = (const float*)d_in[9];
        WB = (const float*)d_in[10]; bB = (const float*)d_in[11];
        WC = (const float*)d_in[12]; bC = (const float*)d_in[13];
        WDl = (const float*)d_in[14]; bDl = (const float*)d_in[15];
        WEl = (const float*)d_in[16]; bEl = (const float*)d_in[17];
        gh = (const float*)d_in[18]; bh = (const float*)d_in[19];
        ge = (const float*)d_in[20]; be = (const float*)d_in[21];
        W0 = (const float*)d_in[22]; b0 = (const float*)d_in[23];
        W1 = (const float*)d_in[24]; b1 = (const float*)d_in[25];
        W2 = (const float*)d_in[26]; b2 = (const float*)d_in[27];
        src = (const int*)d_in[28]; dst = (const int*)d_in[29]; gid = (const int*)d_in[30];
    }
    float* out = (float*)d_out;

    // device scratch addresses
    float *ph, *pA, *pB, *pD, *pE, *pe, *penew;
    cudaGetSymbolAddress((void**)&ph, g_h);
    cudaGetSymbolAddress((void**)&pA, g_A);
    cudaGetSymbolAddress((void**)&pB, g_B);
    cudaGetSymbolAddress((void**)&pD, g_Dh);
    cudaGetSymbolAddress((void**)&pE, g_Eh);
    cudaGetSymbolAddress((void**)&pe, g_e);
    cudaGetSymbolAddress((void**)&penew, g_enew);

    dim3 tb(14, 16);
    const int gemmBlocks = (N + 63) / 64;
    const size_t smem146 = (size_t)(146 * D + 64 * 146) * sizeof(float);
    const size_t smem70  = (size_t)(D * D + 64 * D) * sizeof(float);
    cudaFuncSetAttribute(gemm70_kernel<146>, cudaFuncAttributeMaxDynamicSharedMemorySize, (int)smem146);
    cudaFuncSetAttribute(gemm70_kernel<70>, cudaFuncAttributeMaxDynamicSharedMemorySize, (int)smem70);

    // embeddings
    gemm70_kernel<146><<<gemmBlocks, tb, smem146>>>(nodes, Wemb_h, bemb_h, ph, N);
    embed_e_kernel<<<(E_ + 7) / 8, dim3(D, 8)>>>(ef, Wemb_e, bemb_e, E_);

    const int edgeBlocks = 740;  // 148 SM * 5 (smem-limited occupancy)

    for (int l = 0; l < 4; l++) {
        const float* wA = WA + l * D * D; const float* biA = bA + l * D;
        const float* wB = WB + l * D * D; const float* biB = bB + l * D;
        const float* wC = WC + l * D * D; const float* biC = bC + l * D;
        const float* wD = WDl + l * D * D; const float* biD = bDl + l * D;
        const float* wE = WEl + l * D * D; const float* biE = bEl + l * D;

        gemm70_kernel<70><<<gemmBlocks, tb, smem70>>>(ph, wA, biA, pA, N);
        gemm70_kernel<70><<<gemmBlocks, tb, smem70>>>(ph, wB, biB, pB, N);
        gemm70_kernel<70><<<gemmBlocks, tb, smem70>>>(ph, wD, biD, pD, N);
        gemm70_kernel<70><<<gemmBlocks, tb, smem70>>>(ph, wE, biE, pE, N);

        zero_layer_kernel<<<2048, 256>>>(N * D);

        int storeE = (l < 3) ? 1 : 0;
        edge_kernel<<<edgeBlocks, tb>>>(pe, wC, biC, pD, pE, pB, src, dst, snorm_e,
                                        penew, E_, storeE);

        hcombine_kernel<<<1024, dim3(D, 8)>>>(pA, snorm_n, N);
        finalize_kernel<<<1, D>>>(N, E_);
        happly_kernel<<<(N + 7) / 8, dim3(D, 8)>>>(gh + l * D, bh + l * D, N);
        if (l < 3)
            eapply_kernel<<<(E_ + 7) / 8, dim3(D, 8)>>>(ge + l * D, be + l * D, E_);
    }

    // readout
    zero_readout_kernel<<<(GG * D + 255) / 256, 256>>>();
    scatter_kernel<<<(N + 7) / 8, dim3(D, 8)>>>(gid, N);
    mlp_kernel<<<1, GG>>>(W0, b0, W1, b1, W2, b2, out);
}